// round 1
// baseline (speedup 1.0000x reference)
#include <cuda_runtime.h>
#include <cuda_bf16.h>

#define N_EXPERTS 48
#define D_IN 163840      // 2*1280*8*8
#define D_OUT 2
#define BATCH 512
#define THREADS 256

// Per-sample expert GEMV: out[b, :] = x[b, :] @ W[(t[b]-1)%48] + bias
// x: [B, D_IN] fp32, W: [48, D_IN, 2] fp32, b: [48, 2] fp32, t: [B] int32
__global__ __launch_bounds__(THREADS)
void moe_gemv_kernel(const float* __restrict__ x,
                     const int* __restrict__ t,
                     const float* __restrict__ W,
                     const float* __restrict__ bias,
                     float* __restrict__ out) {
    const int b = blockIdx.x;              // sample index
    const int tid = threadIdx.x;

    // Python-modulo expert index: (t-1) % 48, always non-negative
    int e = t[b] - 1;
    e = ((e % N_EXPERTS) + N_EXPERTS) % N_EXPERTS;

    const float4* __restrict__ xv =
        reinterpret_cast<const float4*>(x + (size_t)b * D_IN);
    const float4* __restrict__ wv =
        reinterpret_cast<const float4*>(W + (size_t)e * D_IN * D_OUT);

    float acc0 = 0.0f, acc1 = 0.0f;

    // D_IN/4 = 40960 float4 chunks; each float4 of x pairs with 2 float4 of W
    // W layout per expert: [d][k], k fastest -> float4 = {W[d,0],W[d,1],W[d+1,0],W[d+1,1]}
    const int n4 = D_IN / 4;
    #pragma unroll 4
    for (int i = tid; i < n4; i += THREADS) {
        float4 xq = xv[i];
        float4 w0 = wv[2 * i];       // d4+0, d4+1
        float4 w1 = wv[2 * i + 1];   // d4+2, d4+3
        acc0 = fmaf(xq.x, w0.x, acc0);
        acc1 = fmaf(xq.x, w0.y, acc1);
        acc0 = fmaf(xq.y, w0.z, acc0);
        acc1 = fmaf(xq.y, w0.w, acc1);
        acc0 = fmaf(xq.z, w1.x, acc0);
        acc1 = fmaf(xq.z, w1.y, acc1);
        acc0 = fmaf(xq.w, w1.z, acc0);
        acc1 = fmaf(xq.w, w1.w, acc1);
    }

    // Warp reduction
    #pragma unroll
    for (int off = 16; off > 0; off >>= 1) {
        acc0 += __shfl_down_sync(0xFFFFFFFFu, acc0, off);
        acc1 += __shfl_down_sync(0xFFFFFFFFu, acc1, off);
    }

    __shared__ float s0[THREADS / 32];
    __shared__ float s1[THREADS / 32];
    const int warp = tid >> 5;
    const int lane = tid & 31;
    if (lane == 0) { s0[warp] = acc0; s1[warp] = acc1; }
    __syncthreads();

    if (warp == 0) {
        constexpr int NW = THREADS / 32;
        acc0 = (lane < NW) ? s0[lane] : 0.0f;
        acc1 = (lane < NW) ? s1[lane] : 0.0f;
        #pragma unroll
        for (int off = NW / 2; off > 0; off >>= 1) {
            acc0 += __shfl_down_sync(0xFFFFFFFFu, acc0, off);
            acc1 += __shfl_down_sync(0xFFFFFFFFu, acc1, off);
        }
        if (lane == 0) {
            out[2 * b + 0] = acc0 + bias[2 * e + 0];
            out[2 * b + 1] = acc1 + bias[2 * e + 1];
        }
    }
}

extern "C" void kernel_launch(void* const* d_in, const int* in_sizes, int n_in,
                              void* d_out, int out_size) {
    const float* x    = (const float*)d_in[0];  // [512, 2,1280,8,8] fp32
    const int*   t    = (const int*)d_in[1];    // [512] int32
    const float* W    = (const float*)d_in[2];  // [48, 163840, 2] fp32
    const float* bias = (const float*)d_in[3];  // [48, 2] fp32
    float* out = (float*)d_out;                 // [512, 2] fp32

    moe_gemv_kernel<<<BATCH, THREADS>>>(x, t, W, bias, out);
}

// round 2
// speedup vs baseline: 1.1356x; 1.1356x over previous
#include <cuda_runtime.h>
#include <cuda_bf16.h>

#define N_EXPERTS 48
#define D_IN 163840      // 2*1280*8*8
#define D_OUT 2
#define BATCH 512
#define THREADS 256
#define NSPLIT 4         // split-K factor -> grid = 512*4 = 2048 CTAs
#define CHUNK (D_IN / NSPLIT)   // 40960 floats per split

// Partial sums: [sample][split][2]  (unique slot per CTA -> deterministic)
__device__ float g_partials[BATCH * NSPLIT * 2];

// Pass 1: each CTA computes a partial dot over one D_IN chunk of one sample.
__global__ __launch_bounds__(THREADS)
void moe_gemv_pass1(const float* __restrict__ x,
                    const int* __restrict__ t,
                    const float* __restrict__ W) {
    const int b     = blockIdx.x >> 2;          // sample index (NSPLIT=4)
    const int split = blockIdx.x & (NSPLIT - 1);
    const int tid   = threadIdx.x;

    // Python-modulo expert index: (t-1) % 48, always non-negative
    int e = t[b] - 1;
    e = ((e % N_EXPERTS) + N_EXPERTS) % N_EXPERTS;

    const int base = split * CHUNK;             // float offset in D_IN
    const float4* __restrict__ xv =
        reinterpret_cast<const float4*>(x + (size_t)b * D_IN + base);
    const float4* __restrict__ wv =
        reinterpret_cast<const float4*>(W + (size_t)e * D_IN * D_OUT
                                          + (size_t)base * D_OUT);

    float acc0 = 0.0f, acc1 = 0.0f;

    const int n4 = CHUNK / 4;                   // 10240 float4 per chunk
    #pragma unroll 4
    for (int i = tid; i < n4; i += THREADS) {
        float4 xq = xv[i];
        float4 w0 = wv[2 * i];       // dims d, d+1: {W[d,0],W[d,1],W[d+1,0],W[d+1,1]}
        float4 w1 = wv[2 * i + 1];   // dims d+2, d+3
        acc0 = fmaf(xq.x, w0.x, acc0);
        acc1 = fmaf(xq.x, w0.y, acc1);
        acc0 = fmaf(xq.y, w0.z, acc0);
        acc1 = fmaf(xq.y, w0.w, acc1);
        acc0 = fmaf(xq.z, w1.x, acc0);
        acc1 = fmaf(xq.z, w1.y, acc1);
        acc0 = fmaf(xq.w, w1.z, acc0);
        acc1 = fmaf(xq.w, w1.w, acc1);
    }

    // Warp reduction
    #pragma unroll
    for (int off = 16; off > 0; off >>= 1) {
        acc0 += __shfl_down_sync(0xFFFFFFFFu, acc0, off);
        acc1 += __shfl_down_sync(0xFFFFFFFFu, acc1, off);
    }

    __shared__ float s0[THREADS / 32];
    __shared__ float s1[THREADS / 32];
    const int warp = tid >> 5;
    const int lane = tid & 31;
    if (lane == 0) { s0[warp] = acc0; s1[warp] = acc1; }
    __syncthreads();

    if (warp == 0) {
        constexpr int NW = THREADS / 32;
        acc0 = (lane < NW) ? s0[lane] : 0.0f;
        acc1 = (lane < NW) ? s1[lane] : 0.0f;
        #pragma unroll
        for (int off = NW / 2; off > 0; off >>= 1) {
            acc0 += __shfl_down_sync(0xFFFFFFFFu, acc0, off);
            acc1 += __shfl_down_sync(0xFFFFFFFFu, acc1, off);
        }
        if (lane == 0) {
            g_partials[(b * NSPLIT + split) * 2 + 0] = acc0;
            g_partials[(b * NSPLIT + split) * 2 + 1] = acc1;
        }
    }
}

// Pass 2: one thread per sample sums NSPLIT partials + bias.
__global__ __launch_bounds__(BATCH)
void moe_gemv_pass2(const int* __restrict__ t,
                    const float* __restrict__ bias,
                    float* __restrict__ out) {
    const int b = threadIdx.x;

    int e = t[b] - 1;
    e = ((e % N_EXPERTS) + N_EXPERTS) % N_EXPERTS;

    float acc0 = 0.0f, acc1 = 0.0f;
    #pragma unroll
    for (int s = 0; s < NSPLIT; s++) {
        acc0 += g_partials[(b * NSPLIT + s) * 2 + 0];
        acc1 += g_partials[(b * NSPLIT + s) * 2 + 1];
    }
    out[2 * b + 0] = acc0 + bias[2 * e + 0];
    out[2 * b + 1] = acc1 + bias[2 * e + 1];
}

extern "C" void kernel_launch(void* const* d_in, const int* in_sizes, int n_in,
                              void* d_out, int out_size) {
    const float* x    = (const float*)d_in[0];  // [512, 2,1280,8,8] fp32
    const int*   t    = (const int*)d_in[1];    // [512] int32
    const float* W    = (const float*)d_in[2];  // [48, 163840, 2] fp32
    const float* bias = (const float*)d_in[3];  // [48, 2] fp32
    float* out = (float*)d_out;                 // [512, 2] fp32

    moe_gemv_pass1<<<BATCH * NSPLIT, THREADS>>>(x, t, W);
    moe_gemv_pass2<<<1, BATCH>>>(t, bias, out);
}

// round 3
// speedup vs baseline: 1.2978x; 1.1429x over previous
#include <cuda_runtime.h>
#include <cuda_bf16.h>

#define N_EXPERTS 48
#define D_IN 163840      // 2*1280*8*8
#define D_OUT 2
#define BATCH 512
#define THREADS 256
#define NSPLIT 8         // split-K factor -> grid = 512*8 = 4096 CTAs
#define CHUNK (D_IN / NSPLIT)   // 20480 floats per split

// Partial sums: [sample][split][2]  (unique slot per CTA -> deterministic)
__device__ float g_partials[BATCH * NSPLIT * 2];
// Per-sample arrival counters (self-resetting -> graph-replay safe)
__device__ int g_count[BATCH];

__global__ __launch_bounds__(THREADS)
void moe_gemv_fused(const float* __restrict__ x,
                    const int* __restrict__ t,
                    const float* __restrict__ W,
                    const float* __restrict__ bias,
                    float* __restrict__ out) {
    const int b     = blockIdx.x >> 3;          // sample index (NSPLIT=8)
    const int split = blockIdx.x & (NSPLIT - 1);
    const int tid   = threadIdx.x;

    // Python-modulo expert index: (t-1) % 48, always non-negative
    int e = t[b] - 1;
    e = ((e % N_EXPERTS) + N_EXPERTS) % N_EXPERTS;

    const int base = split * CHUNK;             // float offset in D_IN
    const float4* __restrict__ xv =
        reinterpret_cast<const float4*>(x + (size_t)b * D_IN + base);
    const float4* __restrict__ wv =
        reinterpret_cast<const float4*>(W + (size_t)e * D_IN * D_OUT
                                          + (size_t)base * D_OUT);

    float acc0 = 0.0f, acc1 = 0.0f;

    const int n4 = CHUNK / 4;                   // 5120 float4 per chunk
    #pragma unroll 4
    for (int i = tid; i < n4; i += THREADS) {
        float4 xq = __ldcs(&xv[i]);             // streamed: read-once, evict-first
        float4 w0 = wv[2 * i];       // dims d, d+1: {W[d,0],W[d,1],W[d+1,0],W[d+1,1]}
        float4 w1 = wv[2 * i + 1];   // dims d+2, d+3
        acc0 = fmaf(xq.x, w0.x, acc0);
        acc1 = fmaf(xq.x, w0.y, acc1);
        acc0 = fmaf(xq.y, w0.z, acc0);
        acc1 = fmaf(xq.y, w0.w, acc1);
        acc0 = fmaf(xq.z, w1.x, acc0);
        acc1 = fmaf(xq.z, w1.y, acc1);
        acc0 = fmaf(xq.w, w1.z, acc0);
        acc1 = fmaf(xq.w, w1.w, acc1);
    }

    // Warp reduction
    #pragma unroll
    for (int off = 16; off > 0; off >>= 1) {
        acc0 += __shfl_down_sync(0xFFFFFFFFu, acc0, off);
        acc1 += __shfl_down_sync(0xFFFFFFFFu, acc1, off);
    }

    __shared__ float s0[THREADS / 32];
    __shared__ float s1[THREADS / 32];
    const int warp = tid >> 5;
    const int lane = tid & 31;
    if (lane == 0) { s0[warp] = acc0; s1[warp] = acc1; }
    __syncthreads();

    if (warp == 0) {
        constexpr int NW = THREADS / 32;
        acc0 = (lane < NW) ? s0[lane] : 0.0f;
        acc1 = (lane < NW) ? s1[lane] : 0.0f;
        #pragma unroll
        for (int off = NW / 2; off > 0; off >>= 1) {
            acc0 += __shfl_down_sync(0xFFFFFFFFu, acc0, off);
            acc1 += __shfl_down_sync(0xFFFFFFFFu, acc1, off);
        }
        if (lane == 0) {
            // Publish this CTA's partial, then take a ticket.
            g_partials[(b * NSPLIT + split) * 2 + 0] = acc0;
            g_partials[(b * NSPLIT + split) * 2 + 1] = acc1;
            __threadfence();
            int old = atomicAdd(&g_count[b], 1);
            if (old == NSPLIT - 1) {
                // Last CTA for this sample: finish. Sum order is fixed
                // (split 0..NSPLIT-1) -> deterministic regardless of arrival.
                g_count[b] = 0;                 // reset for next graph replay
                __threadfence();
                volatile const float* p = g_partials + b * NSPLIT * 2;
                float f0 = 0.0f, f1 = 0.0f;
                #pragma unroll
                for (int s = 0; s < NSPLIT; s++) {
                    f0 += p[2 * s + 0];
                    f1 += p[2 * s + 1];
                }
                out[2 * b + 0] = f0 + bias[2 * e + 0];
                out[2 * b + 1] = f1 + bias[2 * e + 1];
            }
        }
    }
}

extern "C" void kernel_launch(void* const* d_in, const int* in_sizes, int n_in,
                              void* d_out, int out_size) {
    const float* x    = (const float*)d_in[0];  // [512, 2,1280,8,8] fp32
    const int*   t    = (const int*)d_in[1];    // [512] int32
    const float* W    = (const float*)d_in[2];  // [48, 163840, 2] fp32
    const float* bias = (const float*)d_in[3];  // [48, 2] fp32
    float* out = (float*)d_out;                 // [512, 2] fp32

    moe_gemv_fused<<<BATCH * NSPLIT, THREADS>>>(x, t, W, bias, out);
}